// round 1
// baseline (speedup 1.0000x reference)
#include <cuda_runtime.h>

// RNN: B=512, S=4096, H=40, fp32.
// out = concat( [B,S,1] outputs , [1,B,H] final hidden )

#define BATCH 512
#define SEQ   4096
#define HID   40
#define NB    4                 // batches per block
#define KCH   64                // timesteps per chunk (ring depth)
#define THREADS (NB * HID)      // 160
#define RING_STRIDE ((KCH + 1) * HID + 8)   // +8 floats pad -> batches land on different banks

__global__ void __launch_bounds__(THREADS, 1) rnn_kernel(
    const float* __restrict__ x,       // [B, S]
    const float* __restrict__ hidden,  // [B, H]
    const float* __restrict__ w_ih,    // [H]
    const float* __restrict__ w_hh,    // [H, H]
    const float* __restrict__ b_ih,    // [H]
    const float* __restrict__ b_hh,    // [H]
    const float* __restrict__ fc_w,    // [H]
    const float* __restrict__ fc_b,    // [1]
    float* __restrict__ out)           // [B*S] then [B*H]
{
    __shared__ float hring[NB * RING_STRIDE];
    __shared__ float xs[NB][KCH];
    __shared__ float fcw[HID];

    const int tid = threadIdx.x;
    const int b   = tid / HID;              // 0..NB-1
    const int i   = tid % HID;              // 0..39
    const int bg  = blockIdx.x * NB + b;    // global batch

    // W_hh row i in registers
    float w[HID];
#pragma unroll
    for (int j = 0; j < HID; j++) w[j] = w_hh[i * HID + j];
    const float a_ih = w_ih[i];
    const float cbias = b_ih[i] + b_hh[i];
    const float fcb = fc_b[0];
    if (tid < HID) fcw[tid] = fc_w[tid];

    float* ring = &hring[b * RING_STRIDE];
    // slot 0 <- initial hidden
    ring[i] = hidden[bg * HID + i];
    __syncthreads();

    for (int chunk = 0; chunk < SEQ / KCH; chunk++) {
        const int t0 = chunk * KCH;

        // stage x for this chunk
        for (int idx = tid; idx < NB * KCH; idx += THREADS) {
            int bb = idx / KCH, kk = idx % KCH;
            xs[bb][kk] = x[(blockIdx.x * NB + bb) * SEQ + t0 + kk];
        }
        __syncthreads();

#pragma unroll 1
        for (int k = 0; k < KCH; k++) {
            const float xv = xs[b][k];
            float z = fmaf(xv, a_ih, cbias);

            const float4* hp = (const float4*)&ring[k * HID];
            float a0 = 0.f, a1 = 0.f, a2 = 0.f, a3 = 0.f;
            float a4 = 0.f, a5 = 0.f, a6 = 0.f, a7 = 0.f;
#pragma unroll
            for (int j4 = 0; j4 < HID / 8; j4++) {          // 5 iters, 2 float4 each
                float4 h0 = hp[2 * j4 + 0];
                float4 h1 = hp[2 * j4 + 1];
                a0 = fmaf(h0.x, w[8 * j4 + 0], a0);
                a1 = fmaf(h0.y, w[8 * j4 + 1], a1);
                a2 = fmaf(h0.z, w[8 * j4 + 2], a2);
                a3 = fmaf(h0.w, w[8 * j4 + 3], a3);
                a4 = fmaf(h1.x, w[8 * j4 + 4], a4);
                a5 = fmaf(h1.y, w[8 * j4 + 5], a5);
                a6 = fmaf(h1.z, w[8 * j4 + 6], a6);
                a7 = fmaf(h1.w, w[8 * j4 + 7], a7);
            }
            z += ((a0 + a1) + (a2 + a3)) + ((a4 + a5) + (a6 + a7));

            // tanh(z) = 1 - 2/(exp(2z)+1)  (exact at both saturation ends)
            float e = __expf(z + z);
            float hn = 1.0f - __fdividef(2.0f, e + 1.0f);

            ring[(k + 1) * HID + i] = hn;
            __syncthreads();
        }

        // drain: out[b][t0+k] = fcw . h_{t0+k}  (h in slot k+1)
        for (int idx = tid; idx < NB * KCH; idx += THREADS) {
            int bb = idx / KCH, kk = idx % KCH;
            const float* hr = &hring[bb * RING_STRIDE + (kk + 1) * HID];
            float s = 0.f;
#pragma unroll
            for (int j = 0; j < HID; j++) s = fmaf(hr[j], fcw[j], s);
            out[(blockIdx.x * NB + bb) * SEQ + t0 + kk] = s + fcb;
        }

        // carry last h to slot 0 (drain only reads slots 1..K, so no hazard)
        ring[i] = ring[KCH * HID + i];
        __syncthreads();
    }

    // final hidden state h_{S-1} (now in slot 0)
    out[BATCH * SEQ + bg * HID + i] = ring[i];
}

extern "C" void kernel_launch(void* const* d_in, const int* in_sizes, int n_in,
                              void* d_out, int out_size) {
    const float* x      = (const float*)d_in[0];
    const float* hidden = (const float*)d_in[1];
    const float* w_ih   = (const float*)d_in[2];
    const float* w_hh   = (const float*)d_in[3];
    const float* b_ih   = (const float*)d_in[4];
    const float* b_hh   = (const float*)d_in[5];
    const float* fc_w   = (const float*)d_in[6];
    const float* fc_b   = (const float*)d_in[7];
    float* out = (float*)d_out;

    rnn_kernel<<<BATCH / NB, THREADS>>>(x, hidden, w_ih, w_hh, b_ih, b_hh,
                                        fc_w, fc_b, out);
}

// round 2
// speedup vs baseline: 1.0970x; 1.0970x over previous
#include <cuda_runtime.h>

// Vanilla tanh RNN: B=512, S=4096, H=40, fp32.
// out = concat( [B*S] per-step fc outputs , [B*H] final hidden )
//
// Design: one warp per batch (512 warps = 128 CTAs x 4 warps, ~1 warp/SMSP).
// h_t lives in registers, broadcast each step via warp shuffles (no barriers
// in the recurrence loop). Matvec uses packed fma.rn.f32x2 (Blackwell scalar
// FFMA is half-rate). Rows 32..39 are computed redundantly by all lanes
// (row 32+(l&7)) to keep the code uniform and fold-free.
// FC output is deferred: h goes to a shared ring via STS (no sync), drained
// every KCH steps with a single __syncwarp.

#define BATCH 512
#define SEQ   4096
#define HID   40
#define KCH   64
#define WPB   4                   // warps (batches) per block
#define THREADS (WPB * 32)
#define FULLM 0xffffffffu

typedef unsigned long long u64;

__device__ __forceinline__ u64 pack2(float lo, float hi) {
    u64 r;
    asm("mov.b64 %0, {%1, %2};" : "=l"(r) : "f"(lo), "f"(hi));
    return r;
}
__device__ __forceinline__ void unpack2(u64 v, float& lo, float& hi) {
    asm("mov.b64 {%0, %1}, %2;" : "=f"(lo), "=f"(hi) : "l"(v));
}
__device__ __forceinline__ u64 fma2(u64 a, u64 b, u64 c) {
    u64 d;
    asm("fma.rn.f32x2 %0, %1, %2, %3;" : "=l"(d) : "l"(a), "l"(b), "l"(c));
    return d;
}
__device__ __forceinline__ u64 add2(u64 a, u64 b) {
    u64 d;
    asm("add.rn.f32x2 %0, %1, %2;" : "=l"(d) : "l"(a), "l"(b));
    return d;
}
__device__ __forceinline__ float tanh_fast(float z) {
    // tanh(z) = 1 - 2/(exp(2z)+1); exact at both saturation ends.
    float e;
    asm("ex2.approx.f32 %0, %1;" : "=f"(e) : "f"(z * 2.8853900817779268f));
    float r;
    asm("rcp.approx.f32 %0, %1;" : "=f"(r) : "f"(e + 1.0f));
    return fmaf(-2.0f, r, 1.0f);
}

__global__ void __launch_bounds__(THREADS, 1) rnn_kernel(
    const float* __restrict__ x,       // [B, S]
    const float* __restrict__ hidden,  // [B, H]
    const float* __restrict__ w_ih,    // [H]
    const float* __restrict__ w_hh,    // [H, H]
    const float* __restrict__ b_ih,    // [H]
    const float* __restrict__ b_hh,    // [H]
    const float* __restrict__ fc_w,    // [H]
    const float* __restrict__ fc_b,    // [1]
    float* __restrict__ out)           // [B*S] then [B*H]
{
    __shared__ float ring[WPB][KCH * HID];
    __shared__ float fcw_sh[HID];

    const int tid = threadIdx.x;
    const int wid = tid >> 5;
    const int l   = tid & 31;
    const int bg  = blockIdx.x * WPB + wid;       // this warp's batch
    const int rx  = 32 + (l & 7);                 // redundant extra row

    if (tid < HID) fcw_sh[tid] = fc_w[tid];
    __syncthreads();

    // ---- per-lane weights (packed pairs) ----
    u64 wm[HID / 2], wx[HID / 2];
#pragma unroll
    for (int j = 0; j < HID / 2; j++) {
        wm[j] = pack2(w_hh[l * HID + 2 * j],  w_hh[l * HID + 2 * j + 1]);
        wx[j] = pack2(w_hh[rx * HID + 2 * j], w_hh[rx * HID + 2 * j + 1]);
    }
    const float wih_m = w_ih[l],            wih_x = w_ih[rx];
    const float cb_m  = b_ih[l] + b_hh[l],  cb_x  = b_ih[rx] + b_hh[rx];
    const float fcb   = fc_b[0];

    // ---- state in registers ----
    float hm = hidden[bg * HID + l];
    float hx = hidden[bg * HID + rx];

    float* wring = ring[wid];

    // x prefetch for chunk 0
    float xa = x[bg * SEQ + l];
    float xb = x[bg * SEQ + 32 + l];

    for (int chunk = 0; chunk < SEQ / KCH; chunk++) {
        const int t0  = chunk * KCH;
        const int t0n = (chunk + 1 < SEQ / KCH) ? t0 + KCH : 0;
        // prefetch next chunk's x (consumed after 64 steps)
        float xan = x[bg * SEQ + t0n + l];
        float xbn = x[bg * SEQ + t0n + 32 + l];

#pragma unroll 4
        for (int k = 0; k < KCH; k++) {
            float xv = __shfl_sync(FULLM, (k & 32) ? xb : xa, k & 31);

            // broadcast previous h as packed pairs
            u64 hp[HID / 2];
#pragma unroll
            for (int j = 0; j < 16; j++) {
                float lo = __shfl_sync(FULLM, hm, 2 * j);
                float hi = __shfl_sync(FULLM, hm, 2 * j + 1);
                hp[j] = pack2(lo, hi);
            }
#pragma unroll
            for (int m = 0; m < 4; m++) {
                float lo = __shfl_sync(FULLM, hx, 2 * m);      // h_{32+2m} on lane 2m
                float hi = __shfl_sync(FULLM, hx, 2 * m + 1);  // h_{33+2m} on lane 2m+1
                hp[16 + m] = pack2(lo, hi);
            }

            // z = c + x*w_ih + W_hh . h   (two rows per lane)
            u64 a0 = pack2(fmaf(xv, wih_m, cb_m), 0.0f);
            u64 a1 = 0ull, a2 = 0ull, a3 = 0ull;
            u64 c0 = pack2(fmaf(xv, wih_x, cb_x), 0.0f);
            u64 c1 = 0ull, c2 = 0ull, c3 = 0ull;
#pragma unroll
            for (int j = 0; j < HID / 2; j += 4) {
                a0 = fma2(wm[j + 0], hp[j + 0], a0);
                a1 = fma2(wm[j + 1], hp[j + 1], a1);
                a2 = fma2(wm[j + 2], hp[j + 2], a2);
                a3 = fma2(wm[j + 3], hp[j + 3], a3);
                c0 = fma2(wx[j + 0], hp[j + 0], c0);
                c1 = fma2(wx[j + 1], hp[j + 1], c1);
                c2 = fma2(wx[j + 2], hp[j + 2], c2);
                c3 = fma2(wx[j + 3], hp[j + 3], c3);
            }
            u64 am = add2(add2(a0, a1), add2(a2, a3));
            u64 cm = add2(add2(c0, c1), add2(c2, c3));
            float alo, ahi, clo, chi;
            unpack2(am, alo, ahi);
            unpack2(cm, clo, chi);

            hm = tanh_fast(alo + ahi);
            hx = tanh_fast(clo + chi);

            // fire-and-forget ring store (drained after chunk, sync there)
            wring[k * HID + l] = hm;
            wring[k * HID + rx] = hx;   // 4 lanes write identical value
        }

        __syncwarp();

        // ---- drain: out[t0+k] = fcw . h_k + fcb, two outputs per lane ----
#pragma unroll
        for (int o = 0; o < 2; o++) {
            const int k = l + 32 * o;
            const float* row = &wring[k * HID];
            u64 s0 = 0ull, s1 = 0ull, s2 = 0ull, s3 = 0ull;
#pragma unroll
            for (int j = 0; j < HID / 2; j += 4) {
                float2 h0 = *(const float2*)&row[2 * (j + 0)];
                float2 h1 = *(const float2*)&row[2 * (j + 1)];
                float2 h2 = *(const float2*)&row[2 * (j + 2)];
                float2 h3 = *(const float2*)&row[2 * (j + 3)];
                float2 f0 = *(const float2*)&fcw_sh[2 * (j + 0)];
                float2 f1 = *(const float2*)&fcw_sh[2 * (j + 1)];
                float2 f2 = *(const float2*)&fcw_sh[2 * (j + 2)];
                float2 f3 = *(const float2*)&fcw_sh[2 * (j + 3)];
                s0 = fma2(pack2(h0.x, h0.y), pack2(f0.x, f0.y), s0);
                s1 = fma2(pack2(h1.x, h1.y), pack2(f1.x, f1.y), s1);
                s2 = fma2(pack2(h2.x, h2.y), pack2(f2.x, f2.y), s2);
                s3 = fma2(pack2(h3.x, h3.y), pack2(f3.x, f3.y), s3);
            }
            u64 s = add2(add2(s0, s1), add2(s2, s3));
            float slo, shi;
            unpack2(s, slo, shi);
            out[bg * SEQ + t0 + k] = slo + shi + fcb;
        }

        __syncwarp();   // ring reused by next chunk

        xa = xan;
        xb = xbn;
    }

    // ---- final hidden ----
    out[BATCH * SEQ + bg * HID + l]  = hm;
    out[BATCH * SEQ + bg * HID + rx] = hx;   // redundant same-value writes
}

extern "C" void kernel_launch(void* const* d_in, const int* in_sizes, int n_in,
                              void* d_out, int out_size) {
    const float* x      = (const float*)d_in[0];
    const float* hidden = (const float*)d_in[1];
    const float* w_ih   = (const float*)d_in[2];
    const float* w_hh   = (const float*)d_in[3];
    const float* b_ih   = (const float*)d_in[4];
    const float* b_hh   = (const float*)d_in[5];
    const float* fc_w   = (const float*)d_in[6];
    const float* fc_b   = (const float*)d_in[7];
    float* out = (float*)d_out;

    rnn_kernel<<<BATCH / WPB, THREADS>>>(x, hidden, w_ih, w_hh, b_ih, b_hh,
                                         fc_w, fc_b, out);
}

// round 3
// speedup vs baseline: 1.3321x; 1.2143x over previous
#include <cuda_runtime.h>

// Vanilla tanh RNN: B=512, S=4096, H=40, fp32.
// out = concat( [B*S] per-step fc outputs , [B*H] final hidden )
//
// One warp per batch (128 CTAs x 4 warps ~= 1 warp/SMSP). h broadcast via a
// 2-slot shared double buffer (STS + warpsync + broadcast LDS.128), matvec in
// packed fma.rn.f32x2. Lanes 0-7 compute rows {l, 32+l}; lanes 8-31's second
// slot is repurposed to compute fc_w . h + fc_b (pre-tanh z on lane 8), so
// the per-step FC output falls out of the same instruction stream and is
// stored one step behind by a predicated STG. No ring, no drain.

#define BATCH 512
#define SEQ   4096
#define HID   40
#define KCH   64
#define WPB   4
#define THREADS (WPB * 32)
#define FULLM 0xffffffffu

typedef unsigned long long u64;

__device__ __forceinline__ u64 pack2(float lo, float hi) {
    u64 r;
    asm("mov.b64 %0, {%1, %2};" : "=l"(r) : "f"(lo), "f"(hi));
    return r;
}
__device__ __forceinline__ void unpack2(u64 v, float& lo, float& hi) {
    asm("mov.b64 {%0, %1}, %2;" : "=f"(lo), "=f"(hi) : "l"(v));
}
__device__ __forceinline__ u64 fma2(u64 a, u64 b, u64 c) {
    u64 d;
    asm("fma.rn.f32x2 %0, %1, %2, %3;" : "=l"(d) : "l"(a), "l"(b), "l"(c));
    return d;
}
__device__ __forceinline__ u64 add2(u64 a, u64 b) {
    u64 d;
    asm("add.rn.f32x2 %0, %1, %2;" : "=l"(d) : "l"(a), "l"(b));
    return d;
}
__device__ __forceinline__ float tanh_fast(float z) {
    // tanh(z) = 1 - 2/(exp(2z)+1); exact at both saturation ends.
    float e;
    asm("ex2.approx.f32 %0, %1;" : "=f"(e) : "f"(z * 2.8853900817779268f));
    float r;
    asm("rcp.approx.f32 %0, %1;" : "=f"(r) : "f"(e + 1.0f));
    return fmaf(-2.0f, r, 1.0f);
}

__global__ void __launch_bounds__(THREADS, 1) rnn_kernel(
    const float* __restrict__ x,       // [B, S]
    const float* __restrict__ hidden,  // [B, H]
    const float* __restrict__ w_ih,    // [H]
    const float* __restrict__ w_hh,    // [H, H]
    const float* __restrict__ b_ih,    // [H]
    const float* __restrict__ b_hh,    // [H]
    const float* __restrict__ fc_w,    // [H]
    const float* __restrict__ fc_b,    // [1]
    float* __restrict__ out)           // [B*S] then [B*H]
{
    __shared__ __align__(16) float buf[WPB][2][HID];

    const int tid = threadIdx.x;
    const int wid = tid >> 5;
    const int l   = tid & 31;
    const int bg  = blockIdx.x * WPB + wid;

    // ---- per-lane weights ----
    u64 wm[HID / 2], wx[HID / 2];
#pragma unroll
    for (int j = 0; j < HID / 2; j++)
        wm[j] = pack2(w_hh[l * HID + 2 * j], w_hh[l * HID + 2 * j + 1]);

    const float* row2;
    float wih_x, cb_x;
    if (l < 8) {            // real rows 32..39
        row2 = &w_hh[(32 + l) * HID];
        wih_x = w_ih[32 + l];
        cb_x = b_ih[32 + l] + b_hh[32 + l];
    } else {                // fc role (lane 8's result is used)
        row2 = fc_w;
        wih_x = 0.0f;
        cb_x = fc_b[0];
    }
#pragma unroll
    for (int j = 0; j < HID / 2; j++)
        wx[j] = pack2(row2[2 * j], row2[2 * j + 1]);

    const float wih_m = w_ih[l];
    const float cb_m  = b_ih[l] + b_hh[l];

    // ---- initial state ----
    float hm = hidden[bg * HID + l];
    float hxv = 0.0f;
    buf[wid][0][l] = hm;
    if (l < 8) {
        hxv = hidden[bg * HID + 32 + l];
        buf[wid][0][32 + l] = hxv;
    }

    float xa = x[bg * SEQ + l];
    float xb = x[bg * SEQ + 32 + l];

    for (int chunk = 0; chunk < SEQ / KCH; chunk++) {
        const int t0  = chunk * KCH;
        const int t0n = (chunk + 1 < SEQ / KCH) ? t0 + KCH : 0;
        float xan = x[bg * SEQ + t0n + l];
        float xbn = x[bg * SEQ + t0n + 32 + l];

#pragma unroll 2
        for (int k = 0; k < KCH; k++) {
            const int cur = k & 1;       // == global step parity (KCH even)
            __syncwarp();

            // broadcast previous h (all lanes same address -> conflict-free)
            const ulonglong2* hb = (const ulonglong2*)buf[wid][cur];
            u64 hp[HID / 2];
#pragma unroll
            for (int q = 0; q < HID / 4; q++) {
                ulonglong2 v = hb[q];
                hp[2 * q]     = v.x;
                hp[2 * q + 1] = v.y;
            }

            float xv = __shfl_sync(FULLM, (k & 32) ? xb : xa, k & 31);

            u64 a0 = pack2(fmaf(xv, wih_m, cb_m), 0.0f);
            u64 c0 = pack2(fmaf(xv, wih_x, cb_x), 0.0f);
            u64 a1 = 0ull, a2 = 0ull, a3 = 0ull;
            u64 c1 = 0ull, c2 = 0ull, c3 = 0ull;
#pragma unroll
            for (int j = 0; j < HID / 2; j += 4) {
                a0 = fma2(wm[j + 0], hp[j + 0], a0);
                a1 = fma2(wm[j + 1], hp[j + 1], a1);
                a2 = fma2(wm[j + 2], hp[j + 2], a2);
                a3 = fma2(wm[j + 3], hp[j + 3], a3);
                c0 = fma2(wx[j + 0], hp[j + 0], c0);
                c1 = fma2(wx[j + 1], hp[j + 1], c1);
                c2 = fma2(wx[j + 2], hp[j + 2], c2);
                c3 = fma2(wx[j + 3], hp[j + 3], c3);
            }
            u64 am = add2(add2(a0, a1), add2(a2, a3));
            u64 cm = add2(add2(c0, c1), add2(c2, c3));
            float alo, ahi, clo, chi;
            unpack2(am, alo, ahi);
            unpack2(cm, clo, chi);
            float zm = alo + ahi;
            float zc = clo + chi;        // lane 8: fc_w . h_{t-1} + fc_b

            hm  = tanh_fast(zm);
            hxv = tanh_fast(zc);

            if (l == 8) {                // FC output, one step behind
                int t = t0 + k;
                out[bg * SEQ + (t ? t - 1 : 0)] = zc;
            }

            buf[wid][cur ^ 1][l] = hm;
            if (l < 8) buf[wid][cur ^ 1][32 + l] = hxv;
        }

        xa = xan;
        xb = xbn;
    }

    // ---- epilogue: out[S-1] = fc_w . h_{S-1} + fc_b ----
    __syncwarp();
    {
        const ulonglong2* hb = (const ulonglong2*)buf[wid][0];  // SEQ even
        u64 hp[HID / 2];
#pragma unroll
        for (int q = 0; q < HID / 4; q++) {
            ulonglong2 v = hb[q];
            hp[2 * q]     = v.x;
            hp[2 * q + 1] = v.y;
        }
        u64 c0 = pack2(cb_x, 0.0f), c1 = 0ull, c2 = 0ull, c3 = 0ull;
#pragma unroll
        for (int j = 0; j < HID / 2; j += 4) {
            c0 = fma2(wx[j + 0], hp[j + 0], c0);
            c1 = fma2(wx[j + 1], hp[j + 1], c1);
            c2 = fma2(wx[j + 2], hp[j + 2], c2);
            c3 = fma2(wx[j + 3], hp[j + 3], c3);
        }
        u64 cm = add2(add2(c0, c1), add2(c2, c3));
        float clo, chi;
        unpack2(cm, clo, chi);
        if (l == 8) out[bg * SEQ + SEQ - 1] = clo + chi;
    }

    // ---- final hidden ----
    out[BATCH * SEQ + bg * HID + l] = hm;
    if (l < 8) out[BATCH * SEQ + bg * HID + 32 + l] = hxv;
}

extern "C" void kernel_launch(void* const* d_in, const int* in_sizes, int n_in,
                              void* d_out, int out_size) {
    const float* x      = (const float*)d_in[0];
    const float* hidden = (const float*)d_in[1];
    const float* w_ih   = (const float*)d_in[2];
    const float* w_hh   = (const float*)d_in[3];
    const float* b_ih   = (const float*)d_in[4];
    const float* b_hh   = (const float*)d_in[5];
    const float* fc_w   = (const float*)d_in[6];
    const float* fc_b   = (const float*)d_in[7];
    float* out = (float*)d_out;

    rnn_kernel<<<BATCH / WPB, THREADS>>>(x, hidden, w_ih, w_hh, b_ih, b_hh,
                                         fc_w, fc_b, out);
}